// round 1
// baseline (speedup 1.0000x reference)
#include <cuda_runtime.h>
#include <math.h>

#define HH 128
#define WW 128
#define HW (HH * WW)
#define BB 2

// ---------------- scratch (static device allocations; no runtime alloc) ----
__device__ float g_feat1[BB * 64 * HW];    // after conv1+lrelu
__device__ float g_feat2[BB * 64 * HW];    // after conv2+lrelu
__device__ float g_om[BB * 216 * HW];      // raw conv_om output
__device__ float g_dcnw[8 * 9 * 512];      // repacked dcn weights [(g*9+k)][o*8+c]

// ---------------------------------------------------------------------------
// Generic 3x3 "same" conv, NCHW, input optionally concatenated from up to 3
// tensors along channels. 16x16 spatial tile, 8 output channels per thread.
// ---------------------------------------------------------------------------
__global__ void __launch_bounds__(256) conv3x3_kernel(
    const float* __restrict__ inA, int nA,
    const float* __restrict__ inB, int nB,
    const float* __restrict__ inC, int nC,
    const float* __restrict__ wgt, const float* __restrict__ bias,
    float* __restrict__ out, int IC, int OC, int doLrelu)
{
    const int ocgCount = OC >> 3;
    const int bz  = blockIdx.z;
    const int b   = bz / ocgCount;
    const int oc0 = (bz - b * ocgCount) << 3;

    const int tx = threadIdx.x, ty = threadIdx.y;
    const int tid = ty * 16 + tx;
    const int h0 = blockIdx.y * 16, w0 = blockIdx.x * 16;

    __shared__ float sP[18][20];   // input patch with halo
    __shared__ float sW[8][12];    // 8 oc x 9 weights, padded for float4 reads

    float acc[8];
#pragma unroll
    for (int o = 0; o < 8; o++) acc[o] = 0.f;

    for (int ic = 0; ic < IC; ic++) {
        const float* src;
        if (ic < nA)            src = inA + ((size_t)(b * nA + ic)) * HW;
        else if (ic < nA + nB)  src = inB + ((size_t)(b * nB + (ic - nA))) * HW;
        else                    src = inC + ((size_t)(b * nC + (ic - nA - nB))) * HW;

        __syncthreads();   // previous iteration's smem reads are done
        // stage 18x18 patch (zero-padded)
        for (int i = tid; i < 18 * 18; i += 256) {
            int py = i / 18, px = i - py * 18;
            int gy = h0 + py - 1, gx = w0 + px - 1;
            float v = 0.f;
            if (gy >= 0 && gy < HH && gx >= 0 && gx < WW) v = src[gy * WW + gx];
            sP[py][px] = v;
        }
        // stage 8x9 weights for this input channel
        if (tid < 72) {
            int o = tid / 9, j = tid - o * 9;
            sW[o][j] = wgt[((size_t)(oc0 + o) * IC + ic) * 9 + j];
        }
        __syncthreads();

        const float v00 = sP[ty + 0][tx + 0], v01 = sP[ty + 0][tx + 1], v02 = sP[ty + 0][tx + 2];
        const float v10 = sP[ty + 1][tx + 0], v11 = sP[ty + 1][tx + 1], v12 = sP[ty + 1][tx + 2];
        const float v20 = sP[ty + 2][tx + 0], v21 = sP[ty + 2][tx + 1], v22 = sP[ty + 2][tx + 2];

#pragma unroll
        for (int o = 0; o < 8; o++) {
            float4 wA = *(const float4*)&sW[o][0];
            float4 wB = *(const float4*)&sW[o][4];
            float  w8 = sW[o][8];
            acc[o] += v00 * wA.x + v01 * wA.y + v02 * wA.z
                    + v10 * wA.w + v11 * wB.x + v12 * wB.y
                    + v20 * wB.z + v21 * wB.w + v22 * w8;
        }
    }

    const int h = h0 + ty, w = w0 + tx;
#pragma unroll
    for (int o = 0; o < 8; o++) {
        float r = acc[o] + bias[oc0 + o];
        if (doLrelu) r = (r >= 0.f) ? r : 0.1f * r;
        out[((size_t)(b * OC + oc0 + o)) * HW + h * WW + w] = r;
    }
}

// ---------------------------------------------------------------------------
// Repack dcn_w [o][g*8+c][k] (o*576 + (g*8+c)*9 + k) into
// g_dcnw[(g*9+k)*512 + o*8 + c] for coalesced smem staging in the DCN kernel.
// ---------------------------------------------------------------------------
__global__ void repack_dcnw_kernel(const float* __restrict__ w)
{
    int i = blockIdx.x * blockDim.x + threadIdx.x;   // 0 .. 36863
    if (i >= 8 * 9 * 512) return;
    int gk = i >> 9;           // g*9+k
    int oc = i & 511;          // o*8+c
    int g = gk / 9, k = gk - g * 9;
    int o = oc >> 3, c = oc & 7;
    g_dcnw[i] = w[(size_t)o * 576 + (g * 8 + c) * 9 + k];
}

// ---------------------------------------------------------------------------
// Modulated deformable conv (+ offset assembly, sigmoid mask, final lrelu).
// One thread per pixel; 64 fp32 accumulators; per-g weight slab in smem.
// ---------------------------------------------------------------------------
__global__ void __launch_bounds__(256, 2) dcn_kernel(
    const float* __restrict__ feat,    // ref_fea2X [B,64,H,W]
    const float* __restrict__ om,      // [B,216,H,W]
    const float* __restrict__ flows,   // [B,2,H,W]
    const float* __restrict__ bias,    // [64]
    float* __restrict__ out)           // [B,64,H,W]
{
    const int b  = blockIdx.z;
    const int tx = threadIdx.x, ty = threadIdx.y;
    const int tid = ty * 16 + tx;
    const int h = blockIdx.y * 16 + ty;
    const int w = blockIdx.x * 16 + tx;
    const int pix = h * WW + w;

    __shared__ float sWg[9 * 512];     // weights for one g: [k][o*8+c]

    float acc[64];
#pragma unroll
    for (int o = 0; o < 64; o++) acc[o] = 0.f;

    const float flowX = flows[(b * 2 + 0) * HW + pix];
    const float flowY = flows[(b * 2 + 1) * HW + pix];
    const float* omb = om   + (size_t)b * 216 * HW;
    const float* fb  = feat + (size_t)b * 64 * HW;

    for (int g = 0; g < 8; g++) {
        // stage this group's 9*512 weights (contiguous copy, float4)
        __syncthreads();
        {
            const float4* src4 = (const float4*)(g_dcnw + g * 9 * 512);
            float4* dst4 = (float4*)sWg;
            for (int j = tid; j < 9 * 128; j += 256) dst4[j] = src4[j];
        }
        __syncthreads();

        const float* fgc = fb + (g * 8) * HW;

#pragma unroll
        for (int k = 0; k < 9; k++) {
            const int kh = k / 3, kw = k - kh * 3;
            float dy = omb[(g * 18 + 2 * k + 0) * HW + pix] + flowY;
            float dx = omb[(g * 18 + 2 * k + 1) * HW + pix] + flowX;
            float mv = omb[(144 + g * 9 + k) * HW + pix];
            mv = 1.f / (1.f + __expf(-mv));

            float y = (float)h - 1.f + (float)kh + dy;
            float x = (float)w - 1.f + (float)kw + dx;
            float y0f = floorf(y), x0f = floorf(x);
            int y0 = (int)y0f, x0 = (int)x0f;
            float fy = y - y0f, fx = x - x0f;

            float w00 = (1.f - fy) * (1.f - fx);
            float w01 = (1.f - fy) * fx;
            float w10 = fy * (1.f - fx);
            float w11 = fy * fx;

            const bool iy0 = (y0 >= 0) && (y0 < HH);
            const bool iy1 = (y0 + 1 >= 0) && (y0 + 1 < HH);
            const bool ix0 = (x0 >= 0) && (x0 < WW);
            const bool ix1 = (x0 + 1 >= 0) && (x0 + 1 < WW);
            w00 = (iy0 && ix0) ? w00 * mv : 0.f;
            w01 = (iy0 && ix1) ? w01 * mv : 0.f;
            w10 = (iy1 && ix0) ? w10 * mv : 0.f;
            w11 = (iy1 && ix1) ? w11 * mv : 0.f;

            int yc0 = min(max(y0, 0), HH - 1);
            int yc1 = min(max(y0 + 1, 0), HH - 1);
            int xc0 = min(max(x0, 0), WW - 1);
            int xc1 = min(max(x0 + 1, 0), WW - 1);
            int i00 = yc0 * WW + xc0, i01 = yc0 * WW + xc1;
            int i10 = yc1 * WW + xc0, i11 = yc1 * WW + xc1;

            float val[8];
#pragma unroll
            for (int c = 0; c < 8; c++) {
                const float* fc = fgc + c * HW;
                val[c] = w00 * fc[i00] + w01 * fc[i01]
                       + w10 * fc[i10] + w11 * fc[i11];
            }

            const float4* sW4 = (const float4*)(sWg + k * 512);
#pragma unroll
            for (int o = 0; o < 64; o++) {
                float4 wa = sW4[o * 2 + 0];
                float4 wb = sW4[o * 2 + 1];
                acc[o] += val[0] * wa.x + val[1] * wa.y + val[2] * wa.z + val[3] * wa.w
                        + val[4] * wb.x + val[5] * wb.y + val[6] * wb.z + val[7] * wb.w;
            }
        }
    }

#pragma unroll
    for (int o = 0; o < 64; o++) {
        float r = acc[o] + bias[o];
        r = (r >= 0.f) ? r : 0.1f * r;
        out[((size_t)(b * 64 + o)) * HW + pix] = r;
    }
}

// ---------------------------------------------------------------------------
extern "C" void kernel_launch(void* const* d_in, const int* in_sizes, int n_in,
                              void* d_out, int out_size)
{
    const float* ref_fea2X      = (const float*)d_in[0];
    const float* ref_fea2X_flow = (const float*)d_in[1];
    const float* lr_shake_fea   = (const float*)d_in[2];
    const float* flows          = (const float*)d_in[3];
    const float* w1             = (const float*)d_in[4];
    const float* b1             = (const float*)d_in[5];
    const float* w2             = (const float*)d_in[6];
    const float* b2             = (const float*)d_in[7];
    const float* w_om           = (const float*)d_in[8];
    const float* b_om           = (const float*)d_in[9];
    const float* dcn_w          = (const float*)d_in[10];
    const float* dcn_b          = (const float*)d_in[11];
    float* out = (float*)d_out;

    float *feat1, *feat2, *omb;
    cudaGetSymbolAddress((void**)&feat1, g_feat1);
    cudaGetSymbolAddress((void**)&feat2, g_feat2);
    cudaGetSymbolAddress((void**)&omb,   g_om);

    dim3 thr(16, 16);

    // conv1: concat(ref_fea2X_flow, lr_shake_fea, flows) 130 -> 64, lrelu
    conv3x3_kernel<<<dim3(8, 8, BB * (64 / 8)), thr>>>(
        ref_fea2X_flow, 64, lr_shake_fea, 64, flows, 2,
        w1, b1, feat1, 130, 64, 1);

    // conv2: 64 -> 64, lrelu
    conv3x3_kernel<<<dim3(8, 8, BB * (64 / 8)), thr>>>(
        feat1, 64, (const float*)0, 0, (const float*)0, 0,
        w2, b2, feat2, 64, 64, 1);

    // conv_om: 64 -> 216, raw
    conv3x3_kernel<<<dim3(8, 8, BB * (216 / 8)), thr>>>(
        feat2, 64, (const float*)0, 0, (const float*)0, 0,
        w_om, b_om, omb, 64, 216, 0);

    // repack dcn weights for coalesced staging
    repack_dcnw_kernel<<<(8 * 9 * 512 + 255) / 256, 256>>>(dcn_w);

    // modulated deformable conv + lrelu
    dcn_kernel<<<dim3(8, 8, BB), thr>>>(ref_fea2X, omb, flows, dcn_b, out);
}

// round 2
// speedup vs baseline: 1.2992x; 1.2992x over previous
#include <cuda_runtime.h>
#include <math.h>

#define HH 128
#define WW 128
#define HW (HH * WW)
#define BB 2

// ---------------- scratch (static device allocations; no runtime alloc) ----
__device__ float g_feat1[BB * 64 * HW];    // after conv1+lrelu
__device__ float g_feat2[BB * 64 * HW];    // after conv2+lrelu
__device__ float g_om[BB * 216 * HW];      // raw conv_om output
__device__ float g_dcnw[8 * 9 * 512];      // repacked dcn weights [(g*9+k)][o*8+c]

// ---------------------------------------------------------------------------
// 3x3 "same" conv, NCHW, input concatenated from up to 3 tensors along C.
// 32x32 spatial tile per block; 16x16 threads, each computing a 2x2 pixel
// micro-tile for 8 output channels (32 accumulators). Two input channels are
// staged per __syncthreads pair.
// ---------------------------------------------------------------------------
__global__ void __launch_bounds__(256) conv3x3_kernel(
    const float* __restrict__ inA, int nA,
    const float* __restrict__ inB, int nB,
    const float* __restrict__ inC, int nC,
    const float* __restrict__ wgt, const float* __restrict__ bias,
    float* __restrict__ out, int IC, int OC, int doLrelu)
{
    const int ocgCount = OC >> 3;
    const int bz  = blockIdx.z;
    const int b   = bz / ocgCount;
    const int oc0 = (bz - b * ocgCount) << 3;

    const int tx = threadIdx.x, ty = threadIdx.y;
    const int tid = ty * 16 + tx;
    const int h0 = blockIdx.y * 32, w0 = blockIdx.x * 32;

    __shared__ float sP[2][34][35];   // 2 ics x (32+2 halo), padded row
    __shared__ float sW[2][8][12];    // 2 ics x 8 oc x 9 w, padded for float4

    float acc[8][4];
#pragma unroll
    for (int o = 0; o < 8; o++)
#pragma unroll
        for (int p = 0; p < 4; p++) acc[o][p] = 0.f;

    for (int ic0 = 0; ic0 < IC; ic0 += 2) {
        __syncthreads();   // previous chunk's smem reads done
        // ---- stage 2 input-channel patches (34x34, zero-padded) ----
#pragma unroll
        for (int j = 0; j < 2; j++) {
            const int ic = ic0 + j;
            const float* src;
            if (ic < nA)            src = inA + ((size_t)(b * nA + ic)) * HW;
            else if (ic < nA + nB)  src = inB + ((size_t)(b * nB + (ic - nA))) * HW;
            else                    src = inC + ((size_t)(b * nC + (ic - nA - nB))) * HW;
            for (int i = tid; i < 34 * 34; i += 256) {
                int py = i / 34, px = i - py * 34;
                int gy = h0 + py - 1, gx = w0 + px - 1;
                float v = 0.f;
                if (gy >= 0 && gy < HH && gx >= 0 && gx < WW) v = src[gy * WW + gx];
                sP[j][py][px] = v;
            }
        }
        // ---- stage 2x8x9 weights ----
        if (tid < 144) {
            int j = tid / 72, r = tid - j * 72;
            int o = r / 9, q = r - o * 9;
            sW[j][o][q] = wgt[((size_t)(oc0 + o) * IC + (ic0 + j)) * 9 + q];
        }
        __syncthreads();

#pragma unroll
        for (int j = 0; j < 2; j++) {
            // 4x4 patch covering this thread's 2x2 output pixels
            float v[4][4];
#pragma unroll
            for (int r = 0; r < 4; r++)
#pragma unroll
                for (int c = 0; c < 4; c++)
                    v[r][c] = sP[j][2 * ty + r][2 * tx + c];

#pragma unroll
            for (int o = 0; o < 8; o++) {
                float4 wA = *(const float4*)&sW[j][o][0];
                float4 wB = *(const float4*)&sW[j][o][4];
                float  w8 = sW[j][o][8];
#pragma unroll
                for (int r = 0; r < 2; r++)
#pragma unroll
                    for (int c = 0; c < 2; c++) {
                        float s;
                        s  = v[r + 0][c + 0] * wA.x;
                        s += v[r + 0][c + 1] * wA.y;
                        s += v[r + 0][c + 2] * wA.z;
                        s += v[r + 1][c + 0] * wA.w;
                        s += v[r + 1][c + 1] * wB.x;
                        s += v[r + 1][c + 2] * wB.y;
                        s += v[r + 2][c + 0] * wB.z;
                        s += v[r + 2][c + 1] * wB.w;
                        s += v[r + 2][c + 2] * w8;
                        acc[o][r * 2 + c] += s;
                    }
            }
        }
    }

    // ---- epilogue: bias, lrelu, float2 stores ----
#pragma unroll
    for (int o = 0; o < 8; o++) {
        float bv = bias[oc0 + o];
        float* dst = out + ((size_t)(b * OC + oc0 + o)) * HW;
#pragma unroll
        for (int r = 0; r < 2; r++) {
            float r0 = acc[o][r * 2 + 0] + bv;
            float r1 = acc[o][r * 2 + 1] + bv;
            if (doLrelu) {
                r0 = (r0 >= 0.f) ? r0 : 0.1f * r0;
                r1 = (r1 >= 0.f) ? r1 : 0.1f * r1;
            }
            float2 v2 = make_float2(r0, r1);
            *(float2*)&dst[(h0 + 2 * ty + r) * WW + (w0 + 2 * tx)] = v2;
        }
    }
}

// ---------------------------------------------------------------------------
// Repack dcn_w [o][g*8+c][k] into g_dcnw[(g*9+k)*512 + o*8 + c].
// ---------------------------------------------------------------------------
__global__ void repack_dcnw_kernel(const float* __restrict__ w)
{
    int i = blockIdx.x * blockDim.x + threadIdx.x;   // 0 .. 36863
    if (i >= 8 * 9 * 512) return;
    int gk = i >> 9;           // g*9+k
    int oc = i & 511;          // o*8+c
    int g = gk / 9, k = gk - g * 9;
    int o = oc >> 3, c = oc & 7;
    g_dcnw[i] = w[(size_t)o * 576 + (g * 8 + c) * 9 + k];
}

// ---------------------------------------------------------------------------
// Modulated deformable conv (+ offset assembly, sigmoid mask, final lrelu).
// One thread per pixel; 64 fp32 accumulators; per-g weight slab in smem.
// ---------------------------------------------------------------------------
__global__ void __launch_bounds__(256, 2) dcn_kernel(
    const float* __restrict__ feat,    // ref_fea2X [B,64,H,W]
    const float* __restrict__ om,      // [B,216,H,W]
    const float* __restrict__ flows,   // [B,2,H,W]
    const float* __restrict__ bias,    // [64]
    float* __restrict__ out)           // [B,64,H,W]
{
    const int b  = blockIdx.z;
    const int tx = threadIdx.x, ty = threadIdx.y;
    const int tid = ty * 16 + tx;
    const int h = blockIdx.y * 16 + ty;
    const int w = blockIdx.x * 16 + tx;
    const int pix = h * WW + w;

    __shared__ float sWg[9 * 512];     // weights for one g: [k][o*8+c]

    float acc[64];
#pragma unroll
    for (int o = 0; o < 64; o++) acc[o] = 0.f;

    const float flowX = flows[(b * 2 + 0) * HW + pix];
    const float flowY = flows[(b * 2 + 1) * HW + pix];
    const float* omb = om   + (size_t)b * 216 * HW;
    const float* fb  = feat + (size_t)b * 64 * HW;

    for (int g = 0; g < 8; g++) {
        __syncthreads();
        {
            const float4* src4 = (const float4*)(g_dcnw + g * 9 * 512);
            float4* dst4 = (float4*)sWg;
            for (int j = tid; j < 9 * 128; j += 256) dst4[j] = src4[j];
        }
        __syncthreads();

        const float* fgc = fb + (g * 8) * HW;

#pragma unroll
        for (int k = 0; k < 9; k++) {
            const int kh = k / 3, kw = k - kh * 3;
            float dy = omb[(g * 18 + 2 * k + 0) * HW + pix] + flowY;
            float dx = omb[(g * 18 + 2 * k + 1) * HW + pix] + flowX;
            float mv = omb[(144 + g * 9 + k) * HW + pix];
            mv = 1.f / (1.f + __expf(-mv));

            float y = (float)h - 1.f + (float)kh + dy;
            float x = (float)w - 1.f + (float)kw + dx;
            float y0f = floorf(y), x0f = floorf(x);
            int y0 = (int)y0f, x0 = (int)x0f;
            float fy = y - y0f, fx = x - x0f;

            float w00 = (1.f - fy) * (1.f - fx);
            float w01 = (1.f - fy) * fx;
            float w10 = fy * (1.f - fx);
            float w11 = fy * fx;

            const bool iy0 = (y0 >= 0) && (y0 < HH);
            const bool iy1 = (y0 + 1 >= 0) && (y0 + 1 < HH);
            const bool ix0 = (x0 >= 0) && (x0 < WW);
            const bool ix1 = (x0 + 1 >= 0) && (x0 + 1 < WW);
            w00 = (iy0 && ix0) ? w00 * mv : 0.f;
            w01 = (iy0 && ix1) ? w01 * mv : 0.f;
            w10 = (iy1 && ix0) ? w10 * mv : 0.f;
            w11 = (iy1 && ix1) ? w11 * mv : 0.f;

            int yc0 = min(max(y0, 0), HH - 1);
            int yc1 = min(max(y0 + 1, 0), HH - 1);
            int xc0 = min(max(x0, 0), WW - 1);
            int xc1 = min(max(x0 + 1, 0), WW - 1);
            int i00 = yc0 * WW + xc0, i01 = yc0 * WW + xc1;
            int i10 = yc1 * WW + xc0, i11 = yc1 * WW + xc1;

            float val[8];
#pragma unroll
            for (int c = 0; c < 8; c++) {
                const float* fc = fgc + c * HW;
                val[c] = w00 * fc[i00] + w01 * fc[i01]
                       + w10 * fc[i10] + w11 * fc[i11];
            }

            const float4* sW4 = (const float4*)(sWg + k * 512);
#pragma unroll
            for (int o = 0; o < 64; o++) {
                float4 wa = sW4[o * 2 + 0];
                float4 wb = sW4[o * 2 + 1];
                acc[o] += val[0] * wa.x + val[1] * wa.y + val[2] * wa.z + val[3] * wa.w
                        + val[4] * wb.x + val[5] * wb.y + val[6] * wb.z + val[7] * wb.w;
            }
        }
    }

#pragma unroll
    for (int o = 0; o < 64; o++) {
        float r = acc[o] + bias[o];
        r = (r >= 0.f) ? r : 0.1f * r;
        out[((size_t)(b * 64 + o)) * HW + pix] = r;
    }
}

// ---------------------------------------------------------------------------
extern "C" void kernel_launch(void* const* d_in, const int* in_sizes, int n_in,
                              void* d_out, int out_size)
{
    const float* ref_fea2X      = (const float*)d_in[0];
    const float* ref_fea2X_flow = (const float*)d_in[1];
    const float* lr_shake_fea   = (const float*)d_in[2];
    const float* flows          = (const float*)d_in[3];
    const float* w1             = (const float*)d_in[4];
    const float* b1             = (const float*)d_in[5];
    const float* w2             = (const float*)d_in[6];
    const float* b2             = (const float*)d_in[7];
    const float* w_om           = (const float*)d_in[8];
    const float* b_om           = (const float*)d_in[9];
    const float* dcn_w          = (const float*)d_in[10];
    const float* dcn_b          = (const float*)d_in[11];
    float* out = (float*)d_out;

    float *feat1, *feat2, *omb;
    cudaGetSymbolAddress((void**)&feat1, g_feat1);
    cudaGetSymbolAddress((void**)&feat2, g_feat2);
    cudaGetSymbolAddress((void**)&omb,   g_om);

    dim3 thr(16, 16);
    dim3 grid32(WW / 32, HH / 32, 1);

    // conv1: concat(ref_fea2X_flow, lr_shake_fea, flows) 130 -> 64, lrelu
    conv3x3_kernel<<<dim3(4, 4, BB * (64 / 8)), thr>>>(
        ref_fea2X_flow, 64, lr_shake_fea, 64, flows, 2,
        w1, b1, feat1, 130, 64, 1);

    // conv2: 64 -> 64, lrelu
    conv3x3_kernel<<<dim3(4, 4, BB * (64 / 8)), thr>>>(
        feat1, 64, (const float*)0, 0, (const float*)0, 0,
        w2, b2, feat2, 64, 64, 1);

    // conv_om: 64 -> 216, raw
    conv3x3_kernel<<<dim3(4, 4, BB * (216 / 8)), thr>>>(
        feat2, 64, (const float*)0, 0, (const float*)0, 0,
        w_om, b_om, omb, 64, 216, 0);

    // repack dcn weights for coalesced staging
    repack_dcnw_kernel<<<(8 * 9 * 512 + 255) / 256, 256>>>(dcn_w);

    // modulated deformable conv + lrelu
    dcn_kernel<<<dim3(8, 8, BB), thr>>>(ref_fea2X, omb, flows, dcn_b, out);
}